// round 3
// baseline (speedup 1.0000x reference)
#include <cuda_runtime.h>
#include <math.h>

#define NB     2
#define SEQ    2048
#define HID    1024
#define NH     16
#define HD     64
#define SCALE  0.25f      /* 1/sqrt(64) / temperature(0.5) */
#define THRESH 0.01f

#define TQ 16             /* query rows per attention block */

/* scratch: projected Q/K/V in [b][h][s][d] layout */
__device__ float g_q[NB * NH * SEQ * HD];
__device__ float g_k[NB * NH * SEQ * HD];
__device__ float g_v[NB * NH * SEQ * HD];

/* ------------------------------------------------------------------ */
/* Projection: C[i][o] = sum_k X[i][k] * W[o][k] + b[o], scattered to  */
/* [b][head][s][d] layout. 64x64 output tile / block, 256 threads,     */
/* 4x4 per thread, K-chunks of 16 staged transposed in smem.           */
/* ------------------------------------------------------------------ */
__global__ __launch_bounds__(256) void proj_kernel(
    const float* __restrict__ X0, const float* __restrict__ W0, const float* __restrict__ b0,
    const float* __restrict__ X1, const float* __restrict__ W1, const float* __restrict__ b1,
    const float* __restrict__ X2, const float* __restrict__ W2, const float* __restrict__ b2)
{
    const int z = blockIdx.z;
    const float* X    = (z == 0) ? X0 : (z == 1) ? X1 : X2;
    const float* W    = (z == 0) ? W0 : (z == 1) ? W1 : W2;
    const float* bias = (z == 0) ? b0 : (z == 1) ? b1 : b2;
    float* OUT        = (z == 0) ? g_q : (z == 1) ? g_k : g_v;

    const int i0 = blockIdx.x * 64;   /* 4096 / 64 = 64 blocks */
    const int o0 = blockIdx.y * 64;   /* 1024 / 64 = 16 blocks */

    __shared__ float Xs[16][68];      /* [kk][row], pad 68 for aligned f4 reads */
    __shared__ float Ws[16][68];

    const int tid = threadIdx.x;
    const int to  = tid & 15;         /* output-col group  (x4) */
    const int ti  = tid >> 4;         /* output-row group  (x4) */

    float acc[4][4] = {};

    for (int k0 = 0; k0 < HID; k0 += 16) {
#pragma unroll
        for (int r = 0; r < 4; r++) {
            int idx = tid + r * 256;          /* 0..1023 */
            int row = idx >> 4, kk = idx & 15;
            Xs[kk][row] = X[(size_t)(i0 + row) * HID + k0 + kk];
            Ws[kk][row] = W[(size_t)(o0 + row) * HID + k0 + kk];
        }
        __syncthreads();
#pragma unroll
        for (int kk = 0; kk < 16; kk++) {
            float4 xv = *(const float4*)&Xs[kk][ti * 4];
            float4 wv = *(const float4*)&Ws[kk][to * 4];
            float ax[4] = {xv.x, xv.y, xv.z, xv.w};
            float aw[4] = {wv.x, wv.y, wv.z, wv.w};
#pragma unroll
            for (int ii = 0; ii < 4; ii++)
#pragma unroll
                for (int oo = 0; oo < 4; oo++)
                    acc[ii][oo] += ax[ii] * aw[oo];
        }
        __syncthreads();
    }

    /* epilogue: add bias, scatter to [b][head][s][d] */
    const int obase = o0 + to * 4;
    const int head  = obase >> 6;
    const int dd    = obase & 63;
    float4 bv = *(const float4*)&bias[obase];
#pragma unroll
    for (int ii = 0; ii < 4; ii++) {
        int i = i0 + ti * 4 + ii;
        int bb = i >> 11, s = i & 2047;
        float4 v;
        v.x = acc[ii][0] + bv.x;
        v.y = acc[ii][1] + bv.y;
        v.z = acc[ii][2] + bv.z;
        v.w = acc[ii][3] + bv.w;
        *(float4*)&OUT[(((size_t)(bb * NH + head) * SEQ + s) * HD) + dd] = v;
    }
}

/* ------------------------------------------------------------------ */
/* Attention: one block = (b,h) x 16 query rows, 512 threads.         */
/* Full 16x2048 score strip lives in smem; softmax + prune + renorm   */
/* in place; weights written to gmem exactly once; out = W @ V.       */
/* ------------------------------------------------------------------ */
#define SKV_F  (128 * 68)          /* V tile dominates: 8704 floats */

__global__ __launch_bounds__(512) void attn_kernel(
    const unsigned char* __restrict__ mask,   /* [B][S], nonzero = masked */
    float* __restrict__ w_out,                /* [B][NH][S][S] */
    float* __restrict__ o_out)                /* [B][S][HID]   */
{
    extern __shared__ float sm[];
    float* sS   = sm;                 /* 16 x 2048 = 32768 f                  */
    float* sQT  = sm + 32768;         /* pass1: [dd][q] pad 20 = 1280 f;      */
                                      /* pass2: reused as reduction buffer    */
    float* sKV  = sm + 34048;         /* K tile pad65 / V tile pad68 (8704 f) */
    unsigned char* sMask = (unsigned char*)(sm + 34048 + SKV_F);   /* 2048 B  */

    const int bh = blockIdx.y;                 /* 0..31 */
    const int bb = bh >> 4;
    const int h  = bh & 15;
    const int q0 = blockIdx.x * TQ;
    const int tid = threadIdx.x;

    const float* Q = g_q + (size_t)bh * SEQ * HD;
    const float* K = g_k + (size_t)bh * SEQ * HD;
    const float* V = g_v + (size_t)bh * SEQ * HD;

    /* mask + Q tile (transposed) */
    for (int i = tid; i < SEQ; i += 512) sMask[i] = mask[bb * SEQ + i];
    for (int idx = tid; idx < TQ * HD; idx += 512) {
        int q = idx >> 6, dd = idx & 63;
        sQT[dd * 20 + q] = Q[(size_t)(q0 + q) * HD + dd];
    }
    __syncthreads();

    /* ---------------- pass 1: scores = (Q K^T) * SCALE --------------- */
    {
        const int kl = tid & 127;     /* local key within 128-tile */
        const int qg = tid >> 7;      /* q group of 4 (0..3)       */
        for (int kt = 0; kt < SEQ; kt += 128) {
#pragma unroll
            for (int r = 0; r < 4; r++) {
                int idx = tid + r * 512;           /* 0..2047 f4 units */
                int k = idx >> 4, c4 = idx & 15;
                float4 kv = *(const float4*)&K[(size_t)(kt + k) * HD + c4 * 4];
                float* dst = &sKV[k * 65 + c4 * 4];
                dst[0] = kv.x; dst[1] = kv.y; dst[2] = kv.z; dst[3] = kv.w;
            }
            __syncthreads();

            float a0 = 0.f, a1 = 0.f, a2 = 0.f, a3 = 0.f;
#pragma unroll
            for (int dd = 0; dd < 64; dd++) {
                float  kv = sKV[kl * 65 + dd];
                float4 qv = *(const float4*)&sQT[dd * 20 + qg * 4];
                a0 += qv.x * kv;
                a1 += qv.y * kv;
                a2 += qv.z * kv;
                a3 += qv.w * kv;
            }
            const int   col = kt + kl;
            const bool  msk = (sMask[col] != 0);
            sS[(qg * 4 + 0) * SEQ + col] = msk ? -1e30f : a0 * SCALE;
            sS[(qg * 4 + 1) * SEQ + col] = msk ? -1e30f : a1 * SCALE;
            sS[(qg * 4 + 2) * SEQ + col] = msk ? -1e30f : a2 * SCALE;
            sS[(qg * 4 + 3) * SEQ + col] = msk ? -1e30f : a3 * SCALE;
            __syncthreads();
        }
    }

    /* ------------- softmax + prune + renorm + write weights ----------
       one warp per query row (16 warps <-> 16 rows)                    */
    {
        const int r = tid >> 5, lane = tid & 31;
        float* row = &sS[r * SEQ];

        float M = -1e30f;
        for (int c = lane; c < SEQ; c += 32) M = fmaxf(M, row[c]);
#pragma unroll
        for (int o = 16; o; o >>= 1) M = fmaxf(M, __shfl_xor_sync(~0u, M, o));

        float D = 0.f;
        for (int c = lane; c < SEQ; c += 32) {
            float e = __expf(row[c] - M);
            row[c] = e;
            D += e;
        }
#pragma unroll
        for (int o = 16; o; o >>= 1) D += __shfl_xor_sync(~0u, D, o);

        const float thr = THRESH * D;   /* keep iff e/D >= 0.01 */
        float l1 = 0.f;
        for (int c = lane; c < SEQ; c += 32) {
            float e = row[c];
            if (e < thr) row[c] = 0.f;
            else         l1 += e;
        }
#pragma unroll
        for (int o = 16; o; o >>= 1) l1 += __shfl_xor_sync(~0u, l1, o);

        const float inv = 1.0f / fmaxf(l1, 1e-12f * D);

        float4* wrow = (float4*)&w_out[((size_t)bh * SEQ + (q0 + r)) * SEQ];
        for (int c4 = lane; c4 < SEQ / 4; c4 += 32) {
            float4 v = ((float4*)row)[c4];
            v.x *= inv; v.y *= inv; v.z *= inv; v.w *= inv;
            ((float4*)row)[c4] = v;
            wrow[c4] = v;
        }
    }
    __syncthreads();

    /* ---------------- pass 2: out = weights @ V (2-way k split) ------ */
    {
        const int half = tid >> 8;        /* 0/1: which 64-row half of tile */
        const int q    = (tid >> 4) & 15;
        const int dg   = tid & 15;        /* d group of 4 */
        float a0 = 0.f, a1 = 0.f, a2 = 0.f, a3 = 0.f;

        for (int kt = 0; kt < SEQ; kt += 128) {
#pragma unroll
            for (int r = 0; r < 4; r++) {
                int idx = tid + r * 512;          /* 0..2047 f4 units */
                int k = idx >> 4, c4 = idx & 15;
                *(float4*)&sKV[k * 68 + c4 * 4] =
                    *(const float4*)&V[(size_t)(kt + k) * HD + c4 * 4];
            }
            __syncthreads();

            const int kbase = half * 64;
#pragma unroll
            for (int kk = 0; kk < 64; kk += 4) {
                float4 wv = *(const float4*)&sS[q * SEQ + kt + kbase + kk];
                float wa[4] = {wv.x, wv.y, wv.z, wv.w};
#pragma unroll
                for (int j = 0; j < 4; j++) {
                    float4 vv = *(const float4*)&sKV[(kbase + kk + j) * 68 + dg * 4];
                    a0 += wa[j] * vv.x;
                    a1 += wa[j] * vv.y;
                    a2 += wa[j] * vv.z;
                    a3 += wa[j] * vv.w;
                }
            }
            __syncthreads();
        }

        /* combine the two k-halves: half 1 dumps partials, half 0 adds */
        float* sRed = sQT;                 /* 1024 floats, free after pass 1 */
        if (half == 1) {
            float4 p = {a0, a1, a2, a3};
            *(float4*)&sRed[(q * 16 + dg) * 4] = p;
        }
        __syncthreads();
        if (half == 0) {
            float4 p = *(const float4*)&sRed[(q * 16 + dg) * 4];
            float4 v;
            v.x = a0 + p.x; v.y = a1 + p.y; v.z = a2 + p.z; v.w = a3 + p.w;
            *(float4*)&o_out[((size_t)(bb * SEQ + q0 + q) * HID) + h * HD + dg * 4] = v;
        }
    }
}

/* ------------------------------------------------------------------ */
extern "C" void kernel_launch(void* const* d_in, const int* in_sizes, int n_in,
                              void* d_out, int out_size)
{
    const float* query = (const float*)d_in[0];
    const float* key   = (const float*)d_in[1];
    const float* value = (const float*)d_in[2];
    const unsigned char* mask = (const unsigned char*)d_in[3];
    const float* Wq = (const float*)d_in[4];
    const float* bq = (const float*)d_in[5];
    const float* Wk = (const float*)d_in[6];
    const float* bk = (const float*)d_in[7];
    const float* Wv = (const float*)d_in[8];
    const float* bv = (const float*)d_in[9];

    float* out = (float*)d_out;                       /* [B,S,H]        */
    float* wts = out + (size_t)NB * SEQ * HID;        /* [B,NH,S,S]     */

    (void)in_sizes; (void)n_in; (void)out_size;

    /* projections: Q,K,V */
    {
        dim3 grid(64, 16, 3);
        proj_kernel<<<grid, 256>>>(query, Wq, bq, key, Wk, bk, value, Wv, bv);
    }

    /* fused attention */
    {
        const int smem_bytes = (34048 + SKV_F) * 4 + 2048;   /* 173056 B */
        cudaFuncSetAttribute(attn_kernel,
                             cudaFuncAttributeMaxDynamicSharedMemorySize,
                             smem_bytes);
        dim3 grid(SEQ / TQ, NB * NH);                 /* 128 x 32 */
        attn_kernel<<<grid, 512, smem_bytes>>>(mask, wts, out);
    }
}